// round 15
// baseline (speedup 1.0000x reference)
#include <cuda_runtime.h>
#include <cuda_fp16.h>
#include <cstdint>

#define TEMP 30.0f

// ---------------- static device scratch ----------------
// aggregated fp16 weights. gmem stage (55296B) per (b,coH,ch):
//   [coHalf(2)][tap(9)][coL(64)] rows of 48B (16 ci halfs + 8 pad)
__device__ __align__(16) __half g_w16[(size_t)32 * 2 * 16 * 27648];
// transposed fp16 x, compact 32B rows: [b][chunk(16)][f(64)][t(64)] x 16 halfs
__device__ __align__(16) __half g_xT[(size_t)32 * 16 * 64 * 64 * 16];

// ---------------- helpers ----------------
__device__ __forceinline__ uint32_t smem_u32(const void* p) {
    uint32_t a;
    asm("{ .reg .u64 t; cvta.to.shared.u64 t, %1; cvt.u32.u64 %0, t; }" : "=r"(a) : "l"(p));
    return a;
}
__device__ __forceinline__ void ldsm_x4(uint32_t addr, uint32_t* r) {
    asm volatile("ldmatrix.sync.aligned.m8n8.x4.shared.b16 {%0,%1,%2,%3}, [%4];"
                 : "=r"(r[0]), "=r"(r[1]), "=r"(r[2]), "=r"(r[3]) : "r"(addr));
}
__device__ __forceinline__ void mma16816(float* d, const uint32_t* a,
                                         const uint32_t* b) {
    asm volatile(
        "mma.sync.aligned.m16n8k16.row.col.f32.f16.f16.f32 "
        "{%0,%1,%2,%3}, {%4,%5,%6,%7}, {%8,%9}, {%0,%1,%2,%3};"
        : "+f"(d[0]), "+f"(d[1]), "+f"(d[2]), "+f"(d[3])
        : "r"(a[0]), "r"(a[1]), "r"(a[2]), "r"(a[3]), "r"(b[0]), "r"(b[1]));
}
__device__ __forceinline__ void bulk_cp(uint32_t dst, const void* src,
                                        uint32_t bytes, uint32_t mbar) {
    asm volatile(
        "cp.async.bulk.shared::cluster.global.mbarrier::complete_tx::bytes "
        "[%0], [%1], %2, [%3];"
        :: "r"(dst), "l"(src), "r"(bytes), "r"(mbar) : "memory");
}
__device__ __forceinline__ void bulk_st(void* gdst, uint32_t ssrc, uint32_t bytes) {
    asm volatile(
        "cp.async.bulk.global.shared::cta.bulk_group [%0], [%1], %2;"
        :: "l"(gdst), "r"(ssrc), "r"(bytes) : "memory");
}
__device__ __forceinline__ void mbar_wait(uint32_t mb, uint32_t parity) {
    asm volatile(
        "{\n .reg .pred P1;\n"
        "W%=:\n mbarrier.try_wait.parity.acquire.cta.shared::cta.b64 P1, [%0], %1, 0x989680;\n"
        "@P1 bra D%=;\n bra W%=;\n D%=:\n}"
        :: "r"(mb), "r"(parity) : "memory");
}

// ---------------------------------------------------------------------------
// Kernel 1: agg v2 — smem-tiled expert aggregation + bulk stores.
// 128 blocks = (bgrp 2, coH 2, coHf 2, ch 16), 512 threads.
// ---------------------------------------------------------------------------
#define AGG_SMEM (147456 + 2 * 27648)

__global__ __launch_bounds__(512, 1) void agg2_kernel(const float* __restrict__ w,
                                                      const float* __restrict__ g,
                                                      const float* __restrict__ dw,
                                                      const float* __restrict__ db) {
    extern __shared__ __align__(16) char asmem[];
    float* s_w = (float*)asmem;                       // [k][c64][ci16][tap9]
    char* stg = asmem + 147456;                       // 2 x 27648B staging
    __shared__ float s_att[32][4];

    const int blk = blockIdx.x;
    const int bgrp = blk >> 6, coH = (blk >> 5) & 1, coHf = (blk >> 4) & 1, ch = blk & 15;
    const int co0 = coH * 128 + coHf * 64, ci0 = ch * 16;
    const int tid = threadIdx.x;

    for (int i = tid; i < 36864; i += 512) {
        int k = i / 9216, r = i - k * 9216;
        int c = r / 144, j = r - c * 144;
        s_w[i] = w[((size_t)(k * 256 + co0 + c) * 256 + ci0) * 9 + j];
    }
    if (tid < 128) {
        int b = tid >> 2, k = tid & 3;
        const float* gb = g + b * 256;
        float s = 0.f;
#pragma unroll 4
        for (int c = 0; c < 256; ++c) s += gb[c] * dw[c * 4 + k];
        s = (s + db[k]) * (1.f / TEMP);
        float m = s;
        m = fmaxf(m, __shfl_xor_sync(~0u, m, 1));
        m = fmaxf(m, __shfl_xor_sync(~0u, m, 2));
        float e = expf(s - m);
        float su = e;
        su += __shfl_xor_sync(~0u, su, 1);
        su += __shfl_xor_sync(~0u, su, 2);
        s_att[b][k] = e / su;
    }
    __syncthreads();

    const int c = tid >> 3, u = tid & 7;
    float wr[2][9][4];
#pragma unroll
    for (int j = 0; j < 2; ++j)
#pragma unroll
        for (int tap = 0; tap < 9; ++tap)
#pragma unroll
            for (int k = 0; k < 4; ++k)
                wr[j][tap][k] = s_w[((k * 64 + c) * 16 + 2 * u + j) * 9 + tap];

    char* gbase = (char*)g_w16 + (size_t)coH * 16 * 55296 + (size_t)ch * 55296 +
                  (size_t)coHf * 27648;
    const int b0 = bgrp * 16;
    for (int bi = 0; bi < 16; ++bi) {
        const int b = b0 + bi, slot = bi & 1;
        if (tid == 0 && bi >= 2)
            asm volatile("cp.async.bulk.wait_group 1;" ::: "memory");
        __syncthreads();
        float a0 = s_att[b][0], a1 = s_att[b][1], a2 = s_att[b][2], a3 = s_att[b][3];
        char* sslot = stg + slot * 27648;
#pragma unroll
        for (int tap = 0; tap < 9; ++tap) {
            float v0 = a0 * wr[0][tap][0] + a1 * wr[0][tap][1] +
                       a2 * wr[0][tap][2] + a3 * wr[0][tap][3];
            float v1 = a0 * wr[1][tap][0] + a1 * wr[1][tap][1] +
                       a2 * wr[1][tap][2] + a3 * wr[1][tap][3];
            *(__half2*)(sslot + (tap * 64 + c) * 48 + u * 4) =
                __floats2half2_rn(v0, v1);
        }
        __syncthreads();
        if (tid == 0) {
            asm volatile("fence.proxy.async.shared::cta;" ::: "memory");
            bulk_st(gbase + (size_t)b * 2 * 16 * 55296,
                    smem_u32(sslot), 27648u);
            asm volatile("cp.async.bulk.commit_group;" ::: "memory");
        }
    }
    if (tid == 0)
        asm volatile("cp.async.bulk.wait_group 0;" ::: "memory");
    __syncthreads();
}

// ---------------------------------------------------------------------------
// Kernel 2: x -> fp16 transposed compact layout, float4 phase-1 loads.
// smem row = 280 halfs (140 words): phase-1 STS conflicts 4-way -> 2-way.
// ---------------------------------------------------------------------------
__global__ void xT_kernel(const float* __restrict__ x) {
    __shared__ __half s[64][280];
    int f = blockIdx.x, b = blockIdx.y, tid = threadIdx.x;
    const float* xb = x + (size_t)b * 1048576 + f * 64;
#pragma unroll
    for (int it = 0; it < 16; ++it) {
        int idx = it * 256 + tid;
        int ci = idx >> 4, t4 = (idx & 15) * 4;
        float4 v = *(const float4*)&xb[(size_t)ci * 4096 + t4];
        s[t4 + 0][ci] = __float2half_rn(v.x);
        s[t4 + 1][ci] = __float2half_rn(v.y);
        s[t4 + 2][ci] = __float2half_rn(v.z);
        s[t4 + 3][ci] = __float2half_rn(v.w);
    }
    __syncthreads();
#pragma unroll
    for (int it = 0; it < 8; ++it) {
        int i = it * 256 + tid;
        int ch = i >> 7, rem = i & 127;
        int t = rem >> 1, q = rem & 1;
        const __half* sp2 = &s[t][ch * 16 + q * 8];
        uint2 lo = *(const uint2*)sp2;
        uint2 hi = *(const uint2*)(sp2 + 4);
        uint4 o = make_uint4(lo.x, lo.y, hi.x, hi.y);
        __half* dst = g_xT +
            (size_t)(((b * 16 + ch) * 64 + f) * 64 + t) * 16 + q * 8;
        *(uint4*)dst = o;
    }
}

// ---------------------------------------------------------------------------
// Kernel 3: conv, warp-specialized, grid = 1024 tiles (R12 best config).
// CTA = (b, coH 128co, 4 fo x 64 t). 288 threads = 8 compute + 1 producer.
// A-stage layout [coHalf][tap][coL64] rows of 48B; B rows 32B compact.
// ---------------------------------------------------------------------------
#define STG_A 55296
#define STG_B 12672
#define NSTG 3
#define B_BASE (NSTG * STG_A)
#define SMEM_CONV (NSTG * (STG_A + STG_B))   // 203904

__global__ __launch_bounds__(288, 1) void conv_kernel(float* __restrict__ out) {
    extern __shared__ __align__(16) char smem[];
    __shared__ __align__(8) uint64_t s_full[NSTG], s_empty[NSTG];
    const int tid = threadIdx.x, wid = tid >> 5, lane = tid & 31;
    const int b = blockIdx.z, coH = blockIdx.y, fo0 = blockIdx.x * 4;
    const uint32_t sb = smem_u32(smem);
    uint32_t full[NSTG], empty[NSTG];
#pragma unroll
    for (int i = 0; i < NSTG; ++i) {
        full[i]  = smem_u32(&s_full[i]);
        empty[i] = smem_u32(&s_empty[i]);
    }

    for (int i = tid; i < NSTG * STG_B / 4; i += 288)
        ((uint32_t*)(smem + B_BASE))[i] = 0u;
    if (tid == 0) {
#pragma unroll
        for (int i = 0; i < NSTG; ++i) {
            asm volatile("mbarrier.init.shared.b64 [%0], 1;" :: "r"(full[i]) : "memory");
            asm volatile("mbarrier.init.shared.b64 [%0], 8;" :: "r"(empty[i]) : "memory");
        }
    }
    __syncthreads();

    const int pLo = (fo0 == 0) ? 1 : 0;
    const int pHi = (fo0 == 60) ? 5 : 6;

    if (wid == 8) {
        if (lane == 0) {
            const __half* wbase = g_w16 + (size_t)((b * 2 + coH) * 16) * 27648;
            const uint32_t txBytes = STG_A + (uint32_t)(pHi - pLo) * 2048u;
            for (int ch = 0; ch < 16; ++ch) {
                const int slot = ch % NSTG;
                mbar_wait(empty[slot], ((ch / NSTG) + 1) & 1);
                asm volatile("mbarrier.arrive.expect_tx.shared.b64 _, [%0], %1;"
                             :: "r"(full[slot]), "r"(txBytes) : "memory");
                bulk_cp(sb + slot * STG_A,
                        wbase + (size_t)ch * 27648, STG_A, full[slot]);
                const uint32_t bd = sb + B_BASE + slot * STG_B;
                for (int p = pLo; p < pHi; ++p) {
                    int fi = fo0 - 1 + p;
                    bulk_cp(bd + p * 2112 + 32,
                            g_xT + (size_t)(((b * 16 + ch) * 64 + fi) * 64) * 16,
                            2048u, full[slot]);
                }
            }
        }
        return;
    }

    const int wco = wid & 1, wfo = wid >> 1;
    float acc[4][8][4];
#pragma unroll
    for (int m = 0; m < 4; ++m)
#pragma unroll
        for (int n = 0; n < 8; ++n)
#pragma unroll
            for (int e = 0; e < 4; ++e) acc[m][n][e] = 0.f;

    const uint32_t aLane = (lane & 15) * 48 + (lane >> 4) * 16;
    const uint32_t bLane = ((lane & 7) + ((lane & 16) >> 1)) * 32 +
                           ((lane & 8) ? 16u : 0u);

    for (int ch = 0; ch < 16; ++ch) {
        const int slot = ch % NSTG;
        mbar_wait(full[slot], (ch / NSTG) & 1);

        const uint32_t As = sb + slot * STG_A + wco * 27648 + aLane;
        const uint32_t Bs = sb + B_BASE + slot * STG_B + (wfo * 2112) + bLane;
#pragma unroll
        for (int kh = 0; kh < 3; ++kh) {
#pragma unroll
            for (int kw = 0; kw < 3; ++kw) {
                const int tap = kh * 3 + kw;
                uint32_t a[4][4];
#pragma unroll
                for (int m = 0; m < 4; ++m)
                    ldsm_x4(As + tap * 3072 + m * 768, a[m]);
                uint32_t bf[4][4];
                const uint32_t Bp = Bs + kh * 2112 + kw * 32;
#pragma unroll
                for (int nt = 0; nt < 4; ++nt)
                    ldsm_x4(Bp + nt * 512, bf[nt]);
#pragma unroll
                for (int m = 0; m < 4; ++m)
#pragma unroll
                    for (int nt = 0; nt < 4; ++nt) {
                        mma16816(acc[m][nt * 2],     a[m], bf[nt]);
                        mma16816(acc[m][nt * 2 + 1], a[m], bf[nt] + 2);
                    }
            }
        }
        if (lane == 0)
            asm volatile("mbarrier.arrive.shared.b64 _, [%0];"
                         :: "r"(empty[slot]) : "memory");
    }

    const int gRow = lane >> 2, col2 = (lane & 3) * 2;
    const int fo = fo0 + wfo;
#pragma unroll
    for (int m = 0; m < 4; ++m) {
        const int co = coH * 128 + wco * 64 + m * 16 + gRow;
#pragma unroll
        for (int nt = 0; nt < 4; ++nt)
#pragma unroll
            for (int j = 0; j < 2; ++j) {
                const int t = nt * 16 + j * 8 + col2;
                const float* d = acc[m][nt * 2 + j];
                size_t o0 = (((size_t)(b * 256 + co)) * 64 + fo) * 64 + t;
                *(float2*)&out[o0] = make_float2(d[0], d[1]);
                size_t o1 = o0 + 8 * 64 * 64;
                *(float2*)&out[o1] = make_float2(d[2], d[3]);
            }
    }
}

// ---------------------------------------------------------------------------
extern "C" void kernel_launch(void* const* d_in, const int* in_sizes, int n_in,
                              void* d_out, int out_size) {
    const float* x  = (const float*)d_in[0];
    const float* g  = (const float*)d_in[1];
    const float* w  = (const float*)d_in[2];
    const float* dw = (const float*)d_in[3];
    const float* db = (const float*)d_in[4];
    float* out = (float*)d_out;

    xT_kernel<<<dim3(64, 32), 256>>>(x);
    cudaFuncSetAttribute(agg2_kernel,
                         cudaFuncAttributeMaxDynamicSharedMemorySize, AGG_SMEM);
    agg2_kernel<<<128, 512, AGG_SMEM>>>(w, g, dw, db);

    cudaFuncSetAttribute(conv_kernel,
                         cudaFuncAttributeMaxDynamicSharedMemorySize, SMEM_CONV);
    conv_kernel<<<dim3(16, 2, 32), 288, SMEM_CONV>>>(out);
}

// round 16
// speedup vs baseline: 1.5545x; 1.5545x over previous
#include <cuda_runtime.h>
#include <cuda_fp16.h>
#include <cstdint>

#define TEMP 30.0f

// ---------------- static device scratch ----------------
// aggregated fp16 weights. gmem stage (55296B) per (b,coH,ch):
//   [coHalf(2)][tap(9)][coL(64)] rows of 48B (16 ci halfs + 8 pad)
__device__ __align__(16) __half g_w16[(size_t)32 * 2 * 16 * 27648];
// transposed fp16 x, compact 32B rows: [b][chunk(16)][f(64)][t(64)] x 16 halfs
__device__ __align__(16) __half g_xT[(size_t)32 * 16 * 64 * 64 * 16];

// ---------------- helpers ----------------
__device__ __forceinline__ uint32_t smem_u32(const void* p) {
    uint32_t a;
    asm("{ .reg .u64 t; cvta.to.shared.u64 t, %1; cvt.u32.u64 %0, t; }" : "=r"(a) : "l"(p));
    return a;
}
__device__ __forceinline__ void ldsm_x4(uint32_t addr, uint32_t* r) {
    asm volatile("ldmatrix.sync.aligned.m8n8.x4.shared.b16 {%0,%1,%2,%3}, [%4];"
                 : "=r"(r[0]), "=r"(r[1]), "=r"(r[2]), "=r"(r[3]) : "r"(addr));
}
__device__ __forceinline__ void mma16816(float* d, const uint32_t* a,
                                         const uint32_t* b) {
    asm volatile(
        "mma.sync.aligned.m16n8k16.row.col.f32.f16.f16.f32 "
        "{%0,%1,%2,%3}, {%4,%5,%6,%7}, {%8,%9}, {%0,%1,%2,%3};"
        : "+f"(d[0]), "+f"(d[1]), "+f"(d[2]), "+f"(d[3])
        : "r"(a[0]), "r"(a[1]), "r"(a[2]), "r"(a[3]), "r"(b[0]), "r"(b[1]));
}
__device__ __forceinline__ void bulk_cp(uint32_t dst, const void* src,
                                        uint32_t bytes, uint32_t mbar) {
    asm volatile(
        "cp.async.bulk.shared::cluster.global.mbarrier::complete_tx::bytes "
        "[%0], [%1], %2, [%3];"
        :: "r"(dst), "l"(src), "r"(bytes), "r"(mbar) : "memory");
}
__device__ __forceinline__ void bulk_st(void* gdst, uint32_t ssrc, uint32_t bytes) {
    asm volatile(
        "cp.async.bulk.global.shared::cta.bulk_group [%0], [%1], %2;"
        :: "l"(gdst), "r"(ssrc), "r"(bytes) : "memory");
}
__device__ __forceinline__ void mbar_wait(uint32_t mb, uint32_t parity) {
    asm volatile(
        "{\n .reg .pred P1;\n"
        "W%=:\n mbarrier.try_wait.parity.acquire.cta.shared::cta.b64 P1, [%0], %1, 0x989680;\n"
        "@P1 bra D%=;\n bra W%=;\n D%=:\n}"
        :: "r"(mb), "r"(parity) : "memory");
}

// ---------------------------------------------------------------------------
// Kernel 1: agg v2 — smem-tiled expert aggregation + bulk stores.
// 128 blocks = (bgrp 2, coH 2, coHf 2, ch 16), 512 threads.
// ---------------------------------------------------------------------------
#define AGG_SMEM (147456 + 2 * 27648)

__global__ __launch_bounds__(512, 1) void agg2_kernel(const float* __restrict__ w,
                                                      const float* __restrict__ g,
                                                      const float* __restrict__ dw,
                                                      const float* __restrict__ db) {
    extern __shared__ __align__(16) char asmem[];
    float* s_w = (float*)asmem;                       // [k][c64][ci16][tap9]
    char* stg = asmem + 147456;                       // 2 x 27648B staging
    __shared__ float s_att[32][4];

    const int blk = blockIdx.x;
    const int bgrp = blk >> 6, coH = (blk >> 5) & 1, coHf = (blk >> 4) & 1, ch = blk & 15;
    const int co0 = coH * 128 + coHf * 64, ci0 = ch * 16;
    const int tid = threadIdx.x;

    for (int i = tid; i < 36864; i += 512) {
        int k = i / 9216, r = i - k * 9216;
        int c = r / 144, j = r - c * 144;
        s_w[i] = w[((size_t)(k * 256 + co0 + c) * 256 + ci0) * 9 + j];
    }
    if (tid < 128) {
        int b = tid >> 2, k = tid & 3;
        const float* gb = g + b * 256;
        float s = 0.f;
#pragma unroll 4
        for (int c = 0; c < 256; ++c) s += gb[c] * dw[c * 4 + k];
        s = (s + db[k]) * (1.f / TEMP);
        float m = s;
        m = fmaxf(m, __shfl_xor_sync(~0u, m, 1));
        m = fmaxf(m, __shfl_xor_sync(~0u, m, 2));
        float e = expf(s - m);
        float su = e;
        su += __shfl_xor_sync(~0u, su, 1);
        su += __shfl_xor_sync(~0u, su, 2);
        s_att[b][k] = e / su;
    }
    __syncthreads();

    const int c = tid >> 3, u = tid & 7;
    float wr[2][9][4];
#pragma unroll
    for (int j = 0; j < 2; ++j)
#pragma unroll
        for (int tap = 0; tap < 9; ++tap)
#pragma unroll
            for (int k = 0; k < 4; ++k)
                wr[j][tap][k] = s_w[((k * 64 + c) * 16 + 2 * u + j) * 9 + tap];

    char* gbase = (char*)g_w16 + (size_t)coH * 16 * 55296 + (size_t)ch * 55296 +
                  (size_t)coHf * 27648;
    const int b0 = bgrp * 16;
    for (int bi = 0; bi < 16; ++bi) {
        const int b = b0 + bi, slot = bi & 1;
        if (tid == 0 && bi >= 2)
            asm volatile("cp.async.bulk.wait_group 1;" ::: "memory");
        __syncthreads();
        float a0 = s_att[b][0], a1 = s_att[b][1], a2 = s_att[b][2], a3 = s_att[b][3];
        char* sslot = stg + slot * 27648;
#pragma unroll
        for (int tap = 0; tap < 9; ++tap) {
            float v0 = a0 * wr[0][tap][0] + a1 * wr[0][tap][1] +
                       a2 * wr[0][tap][2] + a3 * wr[0][tap][3];
            float v1 = a0 * wr[1][tap][0] + a1 * wr[1][tap][1] +
                       a2 * wr[1][tap][2] + a3 * wr[1][tap][3];
            *(__half2*)(sslot + (tap * 64 + c) * 48 + u * 4) =
                __floats2half2_rn(v0, v1);
        }
        __syncthreads();
        if (tid == 0) {
            asm volatile("fence.proxy.async.shared::cta;" ::: "memory");
            bulk_st(gbase + (size_t)b * 2 * 16 * 55296,
                    smem_u32(sslot), 27648u);
            asm volatile("cp.async.bulk.commit_group;" ::: "memory");
        }
    }
    if (tid == 0)
        asm volatile("cp.async.bulk.wait_group 0;" ::: "memory");
    __syncthreads();
}

// ---------------------------------------------------------------------------
// Kernel 2: x -> fp16 transposed compact layout, float4 phase-1 loads
// ---------------------------------------------------------------------------
__global__ void xT_kernel(const float* __restrict__ x) {
    __shared__ __half s[64][276];
    int f = blockIdx.x, b = blockIdx.y, tid = threadIdx.x;
    const float* xb = x + (size_t)b * 1048576 + f * 64;
#pragma unroll
    for (int it = 0; it < 16; ++it) {
        int idx = it * 256 + tid;
        int ci = idx >> 4, t4 = (idx & 15) * 4;
        float4 v = *(const float4*)&xb[(size_t)ci * 4096 + t4];
        s[t4 + 0][ci] = __float2half_rn(v.x);
        s[t4 + 1][ci] = __float2half_rn(v.y);
        s[t4 + 2][ci] = __float2half_rn(v.z);
        s[t4 + 3][ci] = __float2half_rn(v.w);
    }
    __syncthreads();
#pragma unroll
    for (int it = 0; it < 8; ++it) {
        int i = it * 256 + tid;
        int ch = i >> 7, rem = i & 127;
        int t = rem >> 1, q = rem & 1;
        const __half* sp2 = &s[t][ch * 16 + q * 8];
        uint2 lo = *(const uint2*)sp2;
        uint2 hi = *(const uint2*)(sp2 + 4);
        uint4 o = make_uint4(lo.x, lo.y, hi.x, hi.y);
        __half* dst = g_xT +
            (size_t)(((b * 16 + ch) * 64 + f) * 64 + t) * 16 + q * 8;
        *(uint4*)dst = o;
    }
}

// ---------------------------------------------------------------------------
// Kernel 3: conv, warp-specialized (R12 best config, grid = 1024 tiles).
// CTA = (b, coH 128co, 4 fo x 64 t). 288 threads = 8 compute + 1 producer.
// A-stage layout [coHalf][tap][coL64] rows of 48B; B rows 32B compact.
// ---------------------------------------------------------------------------
#define STG_A 55296
#define STG_B 12672
#define NSTG 3
#define B_BASE (NSTG * STG_A)
#define SMEM_CONV (NSTG * (STG_A + STG_B))   // 203904

__global__ __launch_bounds__(288, 1) void conv_kernel(float* __restrict__ out) {
    extern __shared__ __align__(16) char smem[];
    __shared__ __align__(8) uint64_t s_full[NSTG], s_empty[NSTG];
    const int tid = threadIdx.x, wid = tid >> 5, lane = tid & 31;
    const int b = blockIdx.z, coH = blockIdx.y, fo0 = blockIdx.x * 4;
    const uint32_t sb = smem_u32(smem);
    uint32_t full[NSTG], empty[NSTG];
#pragma unroll
    for (int i = 0; i < NSTG; ++i) {
        full[i]  = smem_u32(&s_full[i]);
        empty[i] = smem_u32(&s_empty[i]);
    }

    for (int i = tid; i < NSTG * STG_B / 4; i += 288)
        ((uint32_t*)(smem + B_BASE))[i] = 0u;
    if (tid == 0) {
#pragma unroll
        for (int i = 0; i < NSTG; ++i) {
            asm volatile("mbarrier.init.shared.b64 [%0], 1;" :: "r"(full[i]) : "memory");
            asm volatile("mbarrier.init.shared.b64 [%0], 8;" :: "r"(empty[i]) : "memory");
        }
    }
    __syncthreads();

    const int pLo = (fo0 == 0) ? 1 : 0;
    const int pHi = (fo0 == 60) ? 5 : 6;

    if (wid == 8) {
        if (lane == 0) {
            const __half* wbase = g_w16 + (size_t)((b * 2 + coH) * 16) * 27648;
            const uint32_t txBytes = STG_A + (uint32_t)(pHi - pLo) * 2048u;
            for (int ch = 0; ch < 16; ++ch) {
                const int slot = ch % NSTG;
                mbar_wait(empty[slot], ((ch / NSTG) + 1) & 1);
                asm volatile("mbarrier.arrive.expect_tx.shared.b64 _, [%0], %1;"
                             :: "r"(full[slot]), "r"(txBytes) : "memory");
                bulk_cp(sb + slot * STG_A,
                        wbase + (size_t)ch * 27648, STG_A, full[slot]);
                const uint32_t bd = sb + B_BASE + slot * STG_B;
                for (int p = pLo; p < pHi; ++p) {
                    int fi = fo0 - 1 + p;
                    bulk_cp(bd + p * 2112 + 32,
                            g_xT + (size_t)(((b * 16 + ch) * 64 + fi) * 64) * 16,
                            2048u, full[slot]);
                }
            }
        }
        return;
    }

    const int wco = wid & 1, wfo = wid >> 1;
    float acc[4][8][4];
#pragma unroll
    for (int m = 0; m < 4; ++m)
#pragma unroll
        for (int n = 0; n < 8; ++n)
#pragma unroll
            for (int e = 0; e < 4; ++e) acc[m][n][e] = 0.f;

    const uint32_t aLane = (lane & 15) * 48 + (lane >> 4) * 16;
    const uint32_t bLane = ((lane & 7) + ((lane & 16) >> 1)) * 32 +
                           ((lane & 8) ? 16u : 0u);

    for (int ch = 0; ch < 16; ++ch) {
        const int slot = ch % NSTG;
        mbar_wait(full[slot], (ch / NSTG) & 1);

        const uint32_t As = sb + slot * STG_A + wco * 27648 + aLane;
        const uint32_t Bs = sb + B_BASE + slot * STG_B + (wfo * 2112) + bLane;
#pragma unroll
        for (int kh = 0; kh < 3; ++kh) {
#pragma unroll
            for (int kw = 0; kw < 3; ++kw) {
                const int tap = kh * 3 + kw;
                uint32_t a[4][4];
#pragma unroll
                for (int m = 0; m < 4; ++m)
                    ldsm_x4(As + tap * 3072 + m * 768, a[m]);
                uint32_t bf[4][4];
                const uint32_t Bp = Bs + kh * 2112 + kw * 32;
#pragma unroll
                for (int nt = 0; nt < 4; ++nt)
                    ldsm_x4(Bp + nt * 512, bf[nt]);
#pragma unroll
                for (int m = 0; m < 4; ++m)
#pragma unroll
                    for (int nt = 0; nt < 4; ++nt) {
                        mma16816(acc[m][nt * 2],     a[m], bf[nt]);
                        mma16816(acc[m][nt * 2 + 1], a[m], bf[nt] + 2);
                    }
            }
        }
        if (lane == 0)
            asm volatile("mbarrier.arrive.shared.b64 _, [%0];"
                         :: "r"(empty[slot]) : "memory");
    }

    const int gRow = lane >> 2, col2 = (lane & 3) * 2;
    const int fo = fo0 + wfo;
#pragma unroll
    for (int m = 0; m < 4; ++m) {
        const int co = coH * 128 + wco * 64 + m * 16 + gRow;
#pragma unroll
        for (int nt = 0; nt < 4; ++nt)
#pragma unroll
            for (int j = 0; j < 2; ++j) {
                const int t = nt * 16 + j * 8 + col2;
                const float* d = acc[m][nt * 2 + j];
                size_t o0 = (((size_t)(b * 256 + co)) * 64 + fo) * 64 + t;
                *(float2*)&out[o0] = make_float2(d[0], d[1]);
                size_t o1 = o0 + 8 * 64 * 64;
                *(float2*)&out[o1] = make_float2(d[2], d[3]);
            }
    }
}

// ---------------------------------------------------------------------------
extern "C" void kernel_launch(void* const* d_in, const int* in_sizes, int n_in,
                              void* d_out, int out_size) {
    const float* x  = (const float*)d_in[0];
    const float* g  = (const float*)d_in[1];
    const float* w  = (const float*)d_in[2];
    const float* dw = (const float*)d_in[3];
    const float* db = (const float*)d_in[4];
    float* out = (float*)d_out;

    xT_kernel<<<dim3(64, 32), 256>>>(x);
    cudaFuncSetAttribute(agg2_kernel,
                         cudaFuncAttributeMaxDynamicSharedMemorySize, AGG_SMEM);
    agg2_kernel<<<128, 512, AGG_SMEM>>>(w, g, dw, db);

    cudaFuncSetAttribute(conv_kernel,
                         cudaFuncAttributeMaxDynamicSharedMemorySize, SMEM_CONV);
    conv_kernel<<<dim3(16, 2, 32), 288, SMEM_CONV>>>(out);
}